// round 5
// baseline (speedup 1.0000x reference)
#include <cuda_runtime.h>
#include <cstddef>

// Problem constants
#define BATCH   4
#define NSEQ    4096
#define CDIM    128
#define HEADS   4
#define BN_TOK  (BATCH * NSEQ)          // 16384 tokens

// ---------------------------------------------------------------------------
// Scratch (device globals — no runtime allocation allowed)
// ---------------------------------------------------------------------------
__device__ float g_xf [BN_TOK * CDIM];            // x @ fcl1_w^T + b
__device__ float g_t  [BN_TOK * CDIM];            // relu(pe1) for current head
__device__ float g_xh [BN_TOK * CDIM];            // xf + pe  for current head
__device__ float g_q  [BN_TOK * CDIM];
__device__ float g_k  [BN_TOK * CDIM];
__device__ float g_v  [BN_TOK * CDIM];
__device__ float g_S  [67108864];                 // 4 * 4096 * 4096  (256 MB)
__device__ float g_cat[BN_TOK * 4 * CDIM];        // concat of heads  [BN][512]
__device__ float g_y1 [BN_TOK * CDIM];
__device__ float g_y2 [BN_TOK * CDIM];

// ---------------------------------------------------------------------------
// Generic fp32 GEMM:   C[i][j] = alpha * sum_k A[i][k] * op(B)   (+bias[j]) (+add[i][j])
//   BT = true  : op(B) = B[j][k]  (B row-major [N][K], "NT" — x @ W^T style)
//   BT = false : op(B) = B[k][j]  (B row-major [K][N], "NN" — P @ V style)
// Tiles: 128 (M) x 64 (N) per CTA, BK=16, 256 threads, 8x4 per-thread microtile.
// Requires: M % 128 == 0, N % 64 == 0, K % 16 == 0 (true for all uses here).
// ---------------------------------------------------------------------------
template<bool BT>
__global__ void __launch_bounds__(256)
gemm_kernel(const float* __restrict__ A, int lda, size_t sA,
            const float* __restrict__ B, int ldb, size_t sB,
            float*       __restrict__ C, int ldc, size_t sC,
            int K, float alpha,
            const float* __restrict__ bias,
            const float* __restrict__ addsrc, int ldadd)
{
    const int z = blockIdx.z;
    A += (size_t)z * sA;
    B += (size_t)z * sB;
    C += (size_t)z * sC;

    __shared__ float As[16][128];
    __shared__ float Bs[16][64];

    const int row0 = blockIdx.y * 128;
    const int col0 = blockIdx.x * 64;
    const int t  = threadIdx.x;      // 0..255
    const int tx = t & 15;           // 16 cols of threads  -> 4 output cols each
    const int ty = t >> 4;           // 16 rows of threads  -> 8 output rows each

    float acc[8][4];
#pragma unroll
    for (int i = 0; i < 8; i++)
#pragma unroll
        for (int j = 0; j < 4; j++) acc[i][j] = 0.f;

    for (int k0 = 0; k0 < K; k0 += 16) {
        // ---- stage A tile: 128 rows x 16 k  (8 elems / thread) ----
#pragma unroll
        for (int i = 0; i < 8; i++) {
            int e  = t + i * 256;
            int r  = e >> 4;
            int kk = e & 15;
            As[kk][r] = A[(size_t)(row0 + r) * lda + (k0 + kk)];
        }
        // ---- stage B tile: 16 k x 64 cols  (4 elems / thread) ----
        if (BT) {
#pragma unroll
            for (int i = 0; i < 4; i++) {
                int e  = t + i * 256;
                int c  = e >> 4;
                int kk = e & 15;
                Bs[kk][c] = B[(size_t)(col0 + c) * ldb + (k0 + kk)];
            }
        } else {
#pragma unroll
            for (int i = 0; i < 4; i++) {
                int e  = t + i * 256;
                int kk = e >> 6;
                int c  = e & 63;
                Bs[kk][c] = B[(size_t)(k0 + kk) * ldb + (col0 + c)];
            }
        }
        __syncthreads();

        // ---- microkernel: 8x4 outer products over 16 k-steps ----
#pragma unroll
        for (int kk = 0; kk < 16; kk++) {
            float4 a0 = *(const float4*)&As[kk][ty * 8];
            float4 a1 = *(const float4*)&As[kk][ty * 8 + 4];
            float4 b  = *(const float4*)&Bs[kk][tx * 4];
            float av[8] = {a0.x, a0.y, a0.z, a0.w, a1.x, a1.y, a1.z, a1.w};
            float bv[4] = {b.x, b.y, b.z, b.w};
#pragma unroll
            for (int i = 0; i < 8; i++)
#pragma unroll
                for (int j = 0; j < 4; j++)
                    acc[i][j] = fmaf(av[i], bv[j], acc[i][j]);
        }
        __syncthreads();
    }

    // ---- epilogue ----
    float bb0 = 0.f, bb1 = 0.f, bb2 = 0.f, bb3 = 0.f;
    if (bias) {
        const float* bp = bias + col0 + tx * 4;
        bb0 = bp[0]; bb1 = bp[1]; bb2 = bp[2]; bb3 = bp[3];
    }
#pragma unroll
    for (int i = 0; i < 8; i++) {
        int r = row0 + ty * 8 + i;
        float v0 = acc[i][0] * alpha + bb0;
        float v1 = acc[i][1] * alpha + bb1;
        float v2 = acc[i][2] * alpha + bb2;
        float v3 = acc[i][3] * alpha + bb3;
        if (addsrc) {
            const float* ap = addsrc + (size_t)r * ldadd + col0 + tx * 4;
            v0 += ap[0]; v1 += ap[1]; v2 += ap[2]; v3 += ap[3];
        }
        *(float4*)&C[(size_t)r * ldc + col0 + tx * 4] = make_float4(v0, v1, v2, v3);
    }
}

// ---------------------------------------------------------------------------
// pe1: t[bn][c] = relu( p[bn,:3] . w[c,:3] + b[c] )    (per-head w/b)
// ---------------------------------------------------------------------------
__global__ void pe1_kernel(const float* __restrict__ p,
                           const float* __restrict__ w,   // [C][3]
                           const float* __restrict__ b,   // [C]
                           float* __restrict__ out)       // [BN][C]
{
    int idx = blockIdx.x * blockDim.x + threadIdx.x;
    if (idx >= BN_TOK * CDIM) return;
    int bn = idx >> 7;
    int c  = idx & 127;
    const float* pp = p + bn * 3;
    const float* ww = w + c * 3;
    float v = fmaf(pp[0], ww[0], fmaf(pp[1], ww[1], fmaf(pp[2], ww[2], b[c])));
    out[idx] = fmaxf(v, 0.f);
}

// ---------------------------------------------------------------------------
// Row softmax over 4096 columns, in place. One CTA (256 thr) per row,
// row kept in registers (16 floats / thread).
// ---------------------------------------------------------------------------
__global__ void softmax_kernel(float* __restrict__ S)
{
    const size_t row = blockIdx.x;
    float* r = S + row * (size_t)NSEQ;
    const int t = threadIdx.x;

    float v[16];
    float mx = -1e30f;
#pragma unroll
    for (int i = 0; i < 16; i++) {
        v[i] = r[t + i * 256];
        mx = fmaxf(mx, v[i]);
    }

    __shared__ float red[256];
    red[t] = mx;
    __syncthreads();
#pragma unroll
    for (int s = 128; s > 0; s >>= 1) {
        if (t < s) red[t] = fmaxf(red[t], red[t + s]);
        __syncthreads();
    }
    mx = red[0];
    __syncthreads();

    float sum = 0.f;
#pragma unroll
    for (int i = 0; i < 16; i++) {
        v[i] = __expf(v[i] - mx);
        sum += v[i];
    }
    red[t] = sum;
    __syncthreads();
#pragma unroll
    for (int s = 128; s > 0; s >>= 1) {
        if (t < s) red[t] += red[t + s];
        __syncthreads();
    }
    float inv = 1.0f / red[0];
#pragma unroll
    for (int i = 0; i < 16; i++)
        r[t + i * 256] = v[i] * inv;
}

// ---------------------------------------------------------------------------
// LayerNorm(y) (no affine) + residual x -> out.   One warp per 128-wide row.
// ---------------------------------------------------------------------------
__global__ void ln_kernel(const float* __restrict__ y,
                          const float* __restrict__ x,
                          float* __restrict__ out)
{
    int row  = blockIdx.x * (blockDim.x >> 5) + (threadIdx.x >> 5);
    int lane = threadIdx.x & 31;
    if (row >= BN_TOK) return;

    float4 v = ((const float4*)(y + (size_t)row * CDIM))[lane];
    float s = v.x + v.y + v.z + v.w;
#pragma unroll
    for (int o = 16; o; o >>= 1) s += __shfl_xor_sync(0xffffffff, s, o);
    float mu = s * (1.f / 128.f);

    float dx = v.x - mu, dy = v.y - mu, dz = v.z - mu, dw = v.w - mu;
    float ss = dx * dx + dy * dy + dz * dz + dw * dw;
#pragma unroll
    for (int o = 16; o; o >>= 1) ss += __shfl_xor_sync(0xffffffff, ss, o);
    float rstd = rsqrtf(ss * (1.f / 128.f) + 1e-5f);

    float4 xv = ((const float4*)(x + (size_t)row * CDIM))[lane];
    ((float4*)(out + (size_t)row * CDIM))[lane] =
        make_float4(dx * rstd + xv.x, dy * rstd + xv.y,
                    dz * rstd + xv.z, dw * rstd + xv.w);
}

__global__ void copy_kernel(const float* __restrict__ src,
                            float* __restrict__ dst, int n)
{
    int i = blockIdx.x * blockDim.x + threadIdx.x;
    if (i < n) dst[i] = src[i];
}

// ---------------------------------------------------------------------------
// Launch
// ---------------------------------------------------------------------------
extern "C" void kernel_launch(void* const* d_in, const int* in_sizes, int n_in,
                              void* d_out, int out_size)
{
    (void)in_sizes; (void)n_in; (void)out_size;

    const float* x      = (const float*)d_in[0];
    const float* p      = (const float*)d_in[1];
    const float* fcl1_w = (const float*)d_in[2];
    const float* fcl1_b = (const float*)d_in[3];
    const float* hq_w   = (const float*)d_in[4];
    const float* hq_b   = (const float*)d_in[5];
    const float* hk_w   = (const float*)d_in[6];
    const float* hk_b   = (const float*)d_in[7];
    const float* hv_w   = (const float*)d_in[8];
    const float* hv_b   = (const float*)d_in[9];
    const float* pe1_w  = (const float*)d_in[10];
    const float* pe1_b  = (const float*)d_in[11];
    const float* pe2_w  = (const float*)d_in[12];
    const float* pe2_b  = (const float*)d_in[13];
    const float* mh_w   = (const float*)d_in[14];
    const float* mh_b   = (const float*)d_in[15];
    const float* fcl2_w = (const float*)d_in[16];
    const float* fcl2_b = (const float*)d_in[17];
    float* out = (float*)d_out;

    float *xf, *tb, *xh, *q, *k, *v, *S, *cat, *y1, *y2;
    cudaGetSymbolAddress((void**)&xf,  g_xf);
    cudaGetSymbolAddress((void**)&tb,  g_t);
    cudaGetSymbolAddress((void**)&xh,  g_xh);
    cudaGetSymbolAddress((void**)&q,   g_q);
    cudaGetSymbolAddress((void**)&k,   g_k);
    cudaGetSymbolAddress((void**)&v,   g_v);
    cudaGetSymbolAddress((void**)&S,   g_S);
    cudaGetSymbolAddress((void**)&cat, g_cat);
    cudaGetSymbolAddress((void**)&y1,  g_y1);
    cudaGetSymbolAddress((void**)&y2,  g_y2);

    const dim3 blk(256);
    const dim3 grid_tok(CDIM / 64, BN_TOK / 128, 1);   // (2, 128) token-major GEMMs
    const float scale = 0.088388347648318447f;          // 1/sqrt(128)

    // xf = x @ fcl1_w^T + fcl1_b
    gemm_kernel<true><<<grid_tok, blk>>>(x, CDIM, 0, fcl1_w, CDIM, 0,
                                         xf, CDIM, 0, CDIM, 1.f, fcl1_b,
                                         nullptr, 0);

    for (int h = 0; h < HEADS; h++) {
        const size_t wofs = (size_t)h * CDIM * CDIM;
        const size_t bofs = (size_t)h * CDIM;

        // t = relu(pe1(p))
        pe1_kernel<<<(BN_TOK * CDIM + 255) / 256, 256>>>(
            p, pe1_w + (size_t)h * CDIM * 3, pe1_b + bofs, tb);

        // xh = t @ pe2_w[h]^T + pe2_b[h] + xf
        gemm_kernel<true><<<grid_tok, blk>>>(tb, CDIM, 0, pe2_w + wofs, CDIM, 0,
                                             xh, CDIM, 0, CDIM, 1.f,
                                             pe2_b + bofs, xf, CDIM);

        // q uses hk_* ; k uses hq_*  (faithful to reference's name swap)
        gemm_kernel<true><<<grid_tok, blk>>>(xh, CDIM, 0, hk_w + wofs, CDIM, 0,
                                             q, CDIM, 0, CDIM, 1.f, hk_b + bofs,
                                             nullptr, 0);
        gemm_kernel<true><<<grid_tok, blk>>>(xh, CDIM, 0, hq_w + wofs, CDIM, 0,
                                             k, CDIM, 0, CDIM, 1.f, hq_b + bofs,
                                             nullptr, 0);
        gemm_kernel<true><<<grid_tok, blk>>>(xh, CDIM, 0, hv_w + wofs, CDIM, 0,
                                             v, CDIM, 0, CDIM, 1.f, hv_b + bofs,
                                             nullptr, 0);

        // S[b] = scale * q[b] @ k[b]^T        (batched over z = b)
        gemm_kernel<true><<<dim3(NSEQ / 64, NSEQ / 128, BATCH), blk>>>(
            q, CDIM, (size_t)NSEQ * CDIM,
            k, CDIM, (size_t)NSEQ * CDIM,
            S, NSEQ, (size_t)NSEQ * NSEQ,
            CDIM, scale, nullptr, nullptr, 0);

        // row softmax (in place)
        softmax_kernel<<<BN_TOK, 256>>>(S);

        // O[b] = S[b] @ v[b]  -> cat[:, h*128 : h*128+128]
        gemm_kernel<false><<<dim3(CDIM / 64, NSEQ / 128, BATCH), blk>>>(
            S, NSEQ, (size_t)NSEQ * NSEQ,
            v, CDIM, (size_t)NSEQ * CDIM,
            cat + (size_t)h * CDIM, HEADS * CDIM, (size_t)NSEQ * HEADS * CDIM,
            NSEQ, 1.f, nullptr, nullptr, 0);
    }

    // y1 = cat @ mh_w^T + mh_b      (K = 512)
    gemm_kernel<true><<<grid_tok, blk>>>(cat, HEADS * CDIM, 0, mh_w, HEADS * CDIM, 0,
                                         y1, CDIM, 0, HEADS * CDIM, 1.f, mh_b,
                                         nullptr, 0);
    // y2 = y1 @ fcl2_w^T + fcl2_b
    gemm_kernel<true><<<grid_tok, blk>>>(y1, CDIM, 0, fcl2_w, CDIM, 0,
                                         y2, CDIM, 0, CDIM, 1.f, fcl2_b,
                                         nullptr, 0);

    // out[0 : BN*C]        = LayerNorm(y2) + x
    ln_kernel<<<BN_TOK / 8, 256>>>(y2, x, out);
    // out[BN*C : BN*C+BN*3] = p  (second tuple element)
    copy_kernel<<<(BN_TOK * 3 + 255) / 256, 256>>>(p, out + (size_t)BN_TOK * CDIM,
                                                   BN_TOK * 3);
}

// round 6
// speedup vs baseline: 1.0008x; 1.0008x over previous
#include <cuda_runtime.h>
#include <cstddef>

// Problem constants
#define BATCH   4
#define NSEQ    4096
#define CDIM    128
#define HEADS   4
#define BN_TOK  (BATCH * NSEQ)          // 16384 tokens

// ---------------------------------------------------------------------------
// Scratch (device globals — no runtime allocation allowed)
// ---------------------------------------------------------------------------
__device__ float g_xf [BN_TOK * CDIM];            // x @ fcl1_w^T + b
__device__ float g_t  [BN_TOK * CDIM];            // relu(pe1) for current head
__device__ float g_xh [BN_TOK * CDIM];            // xf + pe  for current head
__device__ float g_q  [BN_TOK * CDIM];
__device__ float g_k  [BN_TOK * CDIM];
__device__ float g_v  [BN_TOK * CDIM];
__device__ float g_S  [67108864];                 // 4 * 4096 * 4096  (256 MB)
__device__ float g_cat[BN_TOK * 4 * CDIM];        // concat of heads  [BN][512]
__device__ float g_y1 [BN_TOK * CDIM];
__device__ float g_y2 [BN_TOK * CDIM];

// ---------------------------------------------------------------------------
// Generic fp32 GEMM:   C[i][j] = alpha * sum_k A[i][k] * op(B)   (+bias[j]) (+add[i][j])
//   BT = true  : op(B) = B[j][k]  (B row-major [N][K], "NT" — x @ W^T style)
//   BT = false : op(B) = B[k][j]  (B row-major [K][N], "NN" — P @ V style)
// Tiles: 128 (M) x 64 (N) per CTA, BK=16, 256 threads, 8x4 per-thread microtile.
// Requires: M % 128 == 0, N % 64 == 0, K % 16 == 0 (true for all uses here).
// ---------------------------------------------------------------------------
template<bool BT>
__global__ void __launch_bounds__(256)
gemm_kernel(const float* __restrict__ A, int lda, size_t sA,
            const float* __restrict__ B, int ldb, size_t sB,
            float*       __restrict__ C, int ldc, size_t sC,
            int K, float alpha,
            const float* __restrict__ bias,
            const float* __restrict__ addsrc, int ldadd)
{
    const int z = blockIdx.z;
    A += (size_t)z * sA;
    B += (size_t)z * sB;
    C += (size_t)z * sC;

    __shared__ float As[16][128];
    __shared__ float Bs[16][64];

    const int row0 = blockIdx.y * 128;
    const int col0 = blockIdx.x * 64;
    const int t  = threadIdx.x;      // 0..255
    const int tx = t & 15;           // 16 cols of threads  -> 4 output cols each
    const int ty = t >> 4;           // 16 rows of threads  -> 8 output rows each

    float acc[8][4];
#pragma unroll
    for (int i = 0; i < 8; i++)
#pragma unroll
        for (int j = 0; j < 4; j++) acc[i][j] = 0.f;

    for (int k0 = 0; k0 < K; k0 += 16) {
        // ---- stage A tile: 128 rows x 16 k  (8 elems / thread) ----
#pragma unroll
        for (int i = 0; i < 8; i++) {
            int e  = t + i * 256;
            int r  = e >> 4;
            int kk = e & 15;
            As[kk][r] = A[(size_t)(row0 + r) * lda + (k0 + kk)];
        }
        // ---- stage B tile: 16 k x 64 cols  (4 elems / thread) ----
        if (BT) {
#pragma unroll
            for (int i = 0; i < 4; i++) {
                int e  = t + i * 256;
                int c  = e >> 4;
                int kk = e & 15;
                Bs[kk][c] = B[(size_t)(col0 + c) * ldb + (k0 + kk)];
            }
        } else {
#pragma unroll
            for (int i = 0; i < 4; i++) {
                int e  = t + i * 256;
                int kk = e >> 6;
                int c  = e & 63;
                Bs[kk][c] = B[(size_t)(k0 + kk) * ldb + (col0 + c)];
            }
        }
        __syncthreads();

        // ---- microkernel: 8x4 outer products over 16 k-steps ----
#pragma unroll
        for (int kk = 0; kk < 16; kk++) {
            float4 a0 = *(const float4*)&As[kk][ty * 8];
            float4 a1 = *(const float4*)&As[kk][ty * 8 + 4];
            float4 b  = *(const float4*)&Bs[kk][tx * 4];
            float av[8] = {a0.x, a0.y, a0.z, a0.w, a1.x, a1.y, a1.z, a1.w};
            float bv[4] = {b.x, b.y, b.z, b.w};
#pragma unroll
            for (int i = 0; i < 8; i++)
#pragma unroll
                for (int j = 0; j < 4; j++)
                    acc[i][j] = fmaf(av[i], bv[j], acc[i][j]);
        }
        __syncthreads();
    }

    // ---- epilogue ----
    float bb0 = 0.f, bb1 = 0.f, bb2 = 0.f, bb3 = 0.f;
    if (bias) {
        const float* bp = bias + col0 + tx * 4;
        bb0 = bp[0]; bb1 = bp[1]; bb2 = bp[2]; bb3 = bp[3];
    }
#pragma unroll
    for (int i = 0; i < 8; i++) {
        int r = row0 + ty * 8 + i;
        float v0 = acc[i][0] * alpha + bb0;
        float v1 = acc[i][1] * alpha + bb1;
        float v2 = acc[i][2] * alpha + bb2;
        float v3 = acc[i][3] * alpha + bb3;
        if (addsrc) {
            const float* ap = addsrc + (size_t)r * ldadd + col0 + tx * 4;
            v0 += ap[0]; v1 += ap[1]; v2 += ap[2]; v3 += ap[3];
        }
        *(float4*)&C[(size_t)r * ldc + col0 + tx * 4] = make_float4(v0, v1, v2, v3);
    }
}

// ---------------------------------------------------------------------------
// pe1: t[bn][c] = relu( p[bn,:3] . w[c,:3] + b[c] )    (per-head w/b)
// ---------------------------------------------------------------------------
__global__ void pe1_kernel(const float* __restrict__ p,
                           const float* __restrict__ w,   // [C][3]
                           const float* __restrict__ b,   // [C]
                           float* __restrict__ out)       // [BN][C]
{
    int idx = blockIdx.x * blockDim.x + threadIdx.x;
    if (idx >= BN_TOK * CDIM) return;
    int bn = idx >> 7;
    int c  = idx & 127;
    const float* pp = p + bn * 3;
    const float* ww = w + c * 3;
    float v = fmaf(pp[0], ww[0], fmaf(pp[1], ww[1], fmaf(pp[2], ww[2], b[c])));
    out[idx] = fmaxf(v, 0.f);
}

// ---------------------------------------------------------------------------
// Row softmax over 4096 columns, in place. One CTA (256 thr) per row,
// row kept in registers (16 floats / thread).
// ---------------------------------------------------------------------------
__global__ void softmax_kernel(float* __restrict__ S)
{
    const size_t row = blockIdx.x;
    float* r = S + row * (size_t)NSEQ;
    const int t = threadIdx.x;

    float v[16];
    float mx = -1e30f;
#pragma unroll
    for (int i = 0; i < 16; i++) {
        v[i] = r[t + i * 256];
        mx = fmaxf(mx, v[i]);
    }

    __shared__ float red[256];
    red[t] = mx;
    __syncthreads();
#pragma unroll
    for (int s = 128; s > 0; s >>= 1) {
        if (t < s) red[t] = fmaxf(red[t], red[t + s]);
        __syncthreads();
    }
    mx = red[0];
    __syncthreads();

    float sum = 0.f;
#pragma unroll
    for (int i = 0; i < 16; i++) {
        v[i] = __expf(v[i] - mx);
        sum += v[i];
    }
    red[t] = sum;
    __syncthreads();
#pragma unroll
    for (int s = 128; s > 0; s >>= 1) {
        if (t < s) red[t] += red[t + s];
        __syncthreads();
    }
    float inv = 1.0f / red[0];
#pragma unroll
    for (int i = 0; i < 16; i++)
        r[t + i * 256] = v[i] * inv;
}

// ---------------------------------------------------------------------------
// LayerNorm(y) (no affine) + residual x -> out.   One warp per 128-wide row.
// ---------------------------------------------------------------------------
__global__ void ln_kernel(const float* __restrict__ y,
                          const float* __restrict__ x,
                          float* __restrict__ out)
{
    int row  = blockIdx.x * (blockDim.x >> 5) + (threadIdx.x >> 5);
    int lane = threadIdx.x & 31;
    if (row >= BN_TOK) return;

    float4 v = ((const float4*)(y + (size_t)row * CDIM))[lane];
    float s = v.x + v.y + v.z + v.w;
#pragma unroll
    for (int o = 16; o; o >>= 1) s += __shfl_xor_sync(0xffffffff, s, o);
    float mu = s * (1.f / 128.f);

    float dx = v.x - mu, dy = v.y - mu, dz = v.z - mu, dw = v.w - mu;
    float ss = dx * dx + dy * dy + dz * dz + dw * dw;
#pragma unroll
    for (int o = 16; o; o >>= 1) ss += __shfl_xor_sync(0xffffffff, ss, o);
    float rstd = rsqrtf(ss * (1.f / 128.f) + 1e-5f);

    float4 xv = ((const float4*)(x + (size_t)row * CDIM))[lane];
    ((float4*)(out + (size_t)row * CDIM))[lane] =
        make_float4(dx * rstd + xv.x, dy * rstd + xv.y,
                    dz * rstd + xv.z, dw * rstd + xv.w);
}

__global__ void copy_kernel(const float* __restrict__ src,
                            float* __restrict__ dst, int n)
{
    int i = blockIdx.x * blockDim.x + threadIdx.x;
    if (i < n) dst[i] = src[i];
}

// ---------------------------------------------------------------------------
// Launch
// ---------------------------------------------------------------------------
extern "C" void kernel_launch(void* const* d_in, const int* in_sizes, int n_in,
                              void* d_out, int out_size)
{
    (void)in_sizes; (void)n_in; (void)out_size;

    const float* x      = (const float*)d_in[0];
    const float* p      = (const float*)d_in[1];
    const float* fcl1_w = (const float*)d_in[2];
    const float* fcl1_b = (const float*)d_in[3];
    const float* hq_w   = (const float*)d_in[4];
    const float* hq_b   = (const float*)d_in[5];
    const float* hk_w   = (const float*)d_in[6];
    const float* hk_b   = (const float*)d_in[7];
    const float* hv_w   = (const float*)d_in[8];
    const float* hv_b   = (const float*)d_in[9];
    const float* pe1_w  = (const float*)d_in[10];
    const float* pe1_b  = (const float*)d_in[11];
    const float* pe2_w  = (const float*)d_in[12];
    const float* pe2_b  = (const float*)d_in[13];
    const float* mh_w   = (const float*)d_in[14];
    const float* mh_b   = (const float*)d_in[15];
    const float* fcl2_w = (const float*)d_in[16];
    const float* fcl2_b = (const float*)d_in[17];
    float* out = (float*)d_out;

    float *xf, *tb, *xh, *q, *k, *v, *S, *cat, *y1, *y2;
    cudaGetSymbolAddress((void**)&xf,  g_xf);
    cudaGetSymbolAddress((void**)&tb,  g_t);
    cudaGetSymbolAddress((void**)&xh,  g_xh);
    cudaGetSymbolAddress((void**)&q,   g_q);
    cudaGetSymbolAddress((void**)&k,   g_k);
    cudaGetSymbolAddress((void**)&v,   g_v);
    cudaGetSymbolAddress((void**)&S,   g_S);
    cudaGetSymbolAddress((void**)&cat, g_cat);
    cudaGetSymbolAddress((void**)&y1,  g_y1);
    cudaGetSymbolAddress((void**)&y2,  g_y2);

    const dim3 blk(256);
    const dim3 grid_tok(CDIM / 64, BN_TOK / 128, 1);   // (2, 128) token-major GEMMs
    const float scale = 0.088388347648318447f;          // 1/sqrt(128)

    // xf = x @ fcl1_w^T + fcl1_b
    gemm_kernel<true><<<grid_tok, blk>>>(x, CDIM, 0, fcl1_w, CDIM, 0,
                                         xf, CDIM, 0, CDIM, 1.f, fcl1_b,
                                         nullptr, 0);

    for (int h = 0; h < HEADS; h++) {
        const size_t wofs = (size_t)h * CDIM * CDIM;
        const size_t bofs = (size_t)h * CDIM;

        // t = relu(pe1(p))
        pe1_kernel<<<(BN_TOK * CDIM + 255) / 256, 256>>>(
            p, pe1_w + (size_t)h * CDIM * 3, pe1_b + bofs, tb);

        // xh = t @ pe2_w[h]^T + pe2_b[h] + xf
        gemm_kernel<true><<<grid_tok, blk>>>(tb, CDIM, 0, pe2_w + wofs, CDIM, 0,
                                             xh, CDIM, 0, CDIM, 1.f,
                                             pe2_b + bofs, xf, CDIM);

        // q uses hk_* ; k uses hq_*  (faithful to reference's name swap)
        gemm_kernel<true><<<grid_tok, blk>>>(xh, CDIM, 0, hk_w + wofs, CDIM, 0,
                                             q, CDIM, 0, CDIM, 1.f, hk_b + bofs,
                                             nullptr, 0);
        gemm_kernel<true><<<grid_tok, blk>>>(xh, CDIM, 0, hq_w + wofs, CDIM, 0,
                                             k, CDIM, 0, CDIM, 1.f, hq_b + bofs,
                                             nullptr, 0);
        gemm_kernel<true><<<grid_tok, blk>>>(xh, CDIM, 0, hv_w + wofs, CDIM, 0,
                                             v, CDIM, 0, CDIM, 1.f, hv_b + bofs,
                                             nullptr, 0);

        // S[b] = scale * q[b] @ k[b]^T        (batched over z = b)
        gemm_kernel<true><<<dim3(NSEQ / 64, NSEQ / 128, BATCH), blk>>>(
            q, CDIM, (size_t)NSEQ * CDIM,
            k, CDIM, (size_t)NSEQ * CDIM,
            S, NSEQ, (size_t)NSEQ * NSEQ,
            CDIM, scale, nullptr, nullptr, 0);

        // row softmax (in place)
        softmax_kernel<<<BN_TOK, 256>>>(S);

        // O[b] = S[b] @ v[b]  -> cat[:, h*128 : h*128+128]
        gemm_kernel<false><<<dim3(CDIM / 64, NSEQ / 128, BATCH), blk>>>(
            S, NSEQ, (size_t)NSEQ * NSEQ,
            v, CDIM, (size_t)NSEQ * CDIM,
            cat + (size_t)h * CDIM, HEADS * CDIM, (size_t)NSEQ * HEADS * CDIM,
            NSEQ, 1.f, nullptr, nullptr, 0);
    }

    // y1 = cat @ mh_w^T + mh_b      (K = 512)
    gemm_kernel<true><<<grid_tok, blk>>>(cat, HEADS * CDIM, 0, mh_w, HEADS * CDIM, 0,
                                         y1, CDIM, 0, HEADS * CDIM, 1.f, mh_b,
                                         nullptr, 0);
    // y2 = y1 @ fcl2_w^T + fcl2_b
    gemm_kernel<true><<<grid_tok, blk>>>(y1, CDIM, 0, fcl2_w, CDIM, 0,
                                         y2, CDIM, 0, CDIM, 1.f, fcl2_b,
                                         nullptr, 0);

    // out[0 : BN*C]        = LayerNorm(y2) + x
    ln_kernel<<<BN_TOK / 8, 256>>>(y2, x, out);
    // out[BN*C : BN*C+BN*3] = p  (second tuple element)
    copy_kernel<<<(BN_TOK * 3 + 255) / 256, 256>>>(p, out + (size_t)BN_TOK * CDIM,
                                                   BN_TOK * 3);
}